// round 2
// baseline (speedup 1.0000x reference)
#include <cuda_runtime.h>
#include <math.h>

#define BATCH 8
#define CCH   512
#define LL    1024

// Scratch (device globals: allocation-free per harness rules)
__device__ float g_xn [BATCH * CCH * LL];        // 16 MB  groupnorm output
__device__ float g_qkv[BATCH * 3 * CCH * LL];    // 48 MB  qkv projections
__device__ float g_att[BATCH * CCH * LL];        // 16 MB  attention output

// ---------------------------------------------------------------------------
// GroupNorm: 32 groups of 16 channels, each group = 16*1024 = 16384 floats.
// One block per (b, group). xn = (x - mu) * rsqrt(var+eps) * gs + gb
// ---------------------------------------------------------------------------
__global__ void __launch_bounds__(256) gn_kernel(const float* __restrict__ x,
                                                 const float* __restrict__ gs,
                                                 const float* __restrict__ gb) {
    int bg = blockIdx.x;          // b*32 + g  (channels within group are contiguous)
    int g  = bg & 31;
    const float4* xp = (const float4*)(x + (size_t)bg * 16 * LL);
    float4*       op = (float4*)(g_xn + (size_t)bg * 16 * LL);
    int tid = threadIdx.x;

    float s = 0.f, ss = 0.f;
    for (int i = tid; i < 4096; i += 256) {
        float4 v = xp[i];
        s  += v.x + v.y + v.z + v.w;
        ss += v.x*v.x + v.y*v.y + v.z*v.z + v.w*v.w;
    }
    #pragma unroll
    for (int o = 16; o > 0; o >>= 1) {
        s  += __shfl_xor_sync(0xffffffffu, s,  o);
        ss += __shfl_xor_sync(0xffffffffu, ss, o);
    }
    __shared__ float red[16];
    int w = tid >> 5;
    if ((tid & 31) == 0) { red[w] = s; red[8 + w] = ss; }
    __syncthreads();
    if (tid == 0) {
        float S = 0.f, SS = 0.f;
        #pragma unroll
        for (int i = 0; i < 8; i++) { S += red[i]; SS += red[8 + i]; }
        float mu  = S * (1.f / 16384.f);
        float var = SS * (1.f / 16384.f) - mu * mu;
        red[0] = mu;
        red[1] = rsqrtf(var + 1e-5f);
    }
    __syncthreads();
    float mu = red[0], rsd = red[1];
    for (int i = tid; i < 4096; i += 256) {
        float4 v = xp[i];
        int c = (g << 4) + (i >> 8);           // 256 float4 per channel row
        float wc = gs[c] * rsd;
        float bc = gb[c] - mu * wc;
        v.x = v.x * wc + bc;  v.y = v.y * wc + bc;
        v.z = v.z * wc + bc;  v.w = v.w * wc + bc;
        op[i] = v;
    }
}

// ---------------------------------------------------------------------------
// SGEMM: C[b] = A[M,K] @ B[b][K,N] + bias (+ residual).  128x128x8 tiles,
// 256 threads, 8x8 per-thread micro-tile. K,M,N all multiples of tile dims.
// ---------------------------------------------------------------------------
template <bool RESID>
__global__ void __launch_bounds__(256) sgemm_kernel(
    const float* __restrict__ A,    // [M,K] weights (shared over batch)
    const float* __restrict__ Bg,   // [batch][K,N]
    const float* __restrict__ bias, // [M]
    const float* __restrict__ Rg,   // [batch][M,N] residual (RESID only)
    float* __restrict__ Cg,         // [batch][M,N]
    int M, int N, int K)
{
    const float* Bp = Bg + (size_t)blockIdx.z * K * N;
    float*       Cp = Cg + (size_t)blockIdx.z * M * N;

    __shared__ float As[8][132];   // transposed A tile, padded (store conflicts)
    __shared__ float Bs[8][128];

    int tid = threadIdx.x;
    int tx = tid & 15, ty = tid >> 4;
    int m0 = blockIdx.y << 7, n0 = blockIdx.x << 7;

    float acc[8][8];
    #pragma unroll
    for (int i = 0; i < 8; i++)
        #pragma unroll
        for (int j = 0; j < 8; j++) acc[i][j] = 0.f;

    int arow = tid >> 1, acol = (tid & 1) << 2;
    int brow = tid >> 5, bcol = (tid & 31) << 2;
    const float* Aptr = A  + (size_t)(m0 + arow) * K + acol;
    const float* Bptr = Bp + (size_t)brow * N + n0 + bcol;

    for (int k0 = 0; k0 < K; k0 += 8) {
        float4 av = *(const float4*)(Aptr + k0);
        float4 bv = *(const float4*)(Bptr + (size_t)k0 * N);
        __syncthreads();
        As[acol + 0][arow] = av.x;
        As[acol + 1][arow] = av.y;
        As[acol + 2][arow] = av.z;
        As[acol + 3][arow] = av.w;
        *(float4*)&Bs[brow][bcol] = bv;
        __syncthreads();
        #pragma unroll
        for (int k = 0; k < 8; k++) {
            float4 a0 = *(float4*)&As[k][ty << 3];
            float4 a1 = *(float4*)&As[k][(ty << 3) + 4];
            float4 b0 = *(float4*)&Bs[k][tx << 3];
            float4 b1 = *(float4*)&Bs[k][(tx << 3) + 4];
            float ar[8] = {a0.x, a0.y, a0.z, a0.w, a1.x, a1.y, a1.z, a1.w};
            float br[8] = {b0.x, b0.y, b0.z, b0.w, b1.x, b1.y, b1.z, b1.w};
            #pragma unroll
            for (int i = 0; i < 8; i++)
                #pragma unroll
                for (int j = 0; j < 8; j++)
                    acc[i][j] = fmaf(ar[i], br[j], acc[i][j]);
        }
    }

    #pragma unroll
    for (int i = 0; i < 8; i++) {
        int m = m0 + (ty << 3) + i;
        float bb = bias[m];
        #pragma unroll
        for (int jj = 0; jj < 2; jj++) {
            int n = n0 + (tx << 3) + (jj << 2);
            float4 r;
            r.x = acc[i][jj*4+0] + bb; r.y = acc[i][jj*4+1] + bb;
            r.z = acc[i][jj*4+2] + bb; r.w = acc[i][jj*4+3] + bb;
            if (RESID) {
                float4 rv = *(const float4*)(Rg + (size_t)blockIdx.z * M * N
                                             + (size_t)m * N + n);
                r.x += rv.x; r.y += rv.y; r.z += rv.z; r.w += rv.w;
            }
            *(float4*)(Cp + (size_t)m * N + n) = r;
        }
    }
}

// ---------------------------------------------------------------------------
// Flash attention, fp32. Block = (t-tile of 64, bh). 16 s-tiles of 64.
// Layout note: qkv reshape splits 1536 into (8 heads, 192): q/k/v channels
// for head h are at rows h*192 + {0,64,128}. Output channel = h*64 + c.
// scale^2 = 1/sqrt(ch) = 0.125, folded into Q at load.
// ---------------------------------------------------------------------------
__global__ void __launch_bounds__(256) attn_kernel(const float* __restrict__ qkv,
                                                   float* __restrict__ out) {
    extern __shared__ float sm[];
    float* Qs   = sm;                    // [64 c][64 t]
    float* Ks   = sm + 4096;             // [64 c][64 s]
    float* VsT  = sm + 8192;             // [64 s][65]  (transposed, padded)
    float* PsT  = sm + 8192 + 4160;      // [64 s][65]  (transposed, padded)
    float* corr = sm + 8192 + 8320;      // [64 t]
    float* lbuf = corr + 64;             // [64 t]

    int bh = blockIdx.y;
    int b = bh >> 3, h = bh & 7;
    int t0 = blockIdx.x << 6;
    const float* qb = qkv + ((size_t)b * 1536 + h * 192) * 1024;
    const float* kb = qb + (size_t)64  * 1024;
    const float* vb = qb + (size_t)128 * 1024;

    int tid = threadIdx.x;
    int tx = tid & 15, ty = tid >> 4;

    // Load Q tile (scaled by 1/8)
    for (int i = tid; i < 1024; i += 256) {
        int r = i >> 4, c4 = (i & 15) << 2;
        float4 v = *(const float4*)(qb + (size_t)r * 1024 + t0 + c4);
        v.x *= 0.125f; v.y *= 0.125f; v.z *= 0.125f; v.w *= 0.125f;
        *(float4*)&Qs[(r << 6) + c4] = v;
    }

    float acc[4][4];
    #pragma unroll
    for (int i = 0; i < 4; i++)
        #pragma unroll
        for (int j = 0; j < 4; j++) acc[i][j] = 0.f;
    float mrow[4] = {-1e30f, -1e30f, -1e30f, -1e30f};
    float lrow[4] = {0.f, 0.f, 0.f, 0.f};

    for (int s0 = 0; s0 < 1024; s0 += 64) {
        __syncthreads();   // prev-iter readers done (also covers Q load 1st iter)
        for (int i = tid; i < 1024; i += 256) {
            int r = i >> 4, c4 = (i & 15) << 2;
            *(float4*)&Ks[(r << 6) + c4] =
                *(const float4*)(kb + (size_t)r * 1024 + s0 + c4);
            float4 v = *(const float4*)(vb + (size_t)r * 1024 + s0 + c4);
            VsT[(c4 + 0) * 65 + r] = v.x;
            VsT[(c4 + 1) * 65 + r] = v.y;
            VsT[(c4 + 2) * 65 + r] = v.z;
            VsT[(c4 + 3) * 65 + r] = v.w;
        }
        __syncthreads();

        // GEMM1: S[t][s] = sum_c Q[c][t]*K[c][s]; thread owns t=ty*4+i, s=tx*4+j
        float sf[4][4];
        #pragma unroll
        for (int i = 0; i < 4; i++)
            #pragma unroll
            for (int j = 0; j < 4; j++) sf[i][j] = 0.f;
        #pragma unroll 8
        for (int k = 0; k < 64; k++) {
            float4 qv = *(float4*)&Qs[(k << 6) + (ty << 2)];
            float4 kv = *(float4*)&Ks[(k << 6) + (tx << 2)];
            float qa[4] = {qv.x, qv.y, qv.z, qv.w};
            float ka[4] = {kv.x, kv.y, kv.z, kv.w};
            #pragma unroll
            for (int i = 0; i < 4; i++)
                #pragma unroll
                for (int j = 0; j < 4; j++)
                    sf[i][j] = fmaf(qa[i], ka[j], sf[i][j]);
        }

        // Online softmax: rows (t) reduced across the 16 tx lanes
        #pragma unroll
        for (int i = 0; i < 4; i++) {
            float mx = fmaxf(fmaxf(sf[i][0], sf[i][1]), fmaxf(sf[i][2], sf[i][3]));
            #pragma unroll
            for (int o = 1; o < 16; o <<= 1)
                mx = fmaxf(mx, __shfl_xor_sync(0xffffffffu, mx, o));
            float mnew = fmaxf(mrow[i], mx);
            float cf = __expf(mrow[i] - mnew);
            mrow[i] = mnew;
            float rs = 0.f;
            #pragma unroll
            for (int j = 0; j < 4; j++) {
                float p = __expf(sf[i][j] - mnew);
                sf[i][j] = p;
                rs += p;
            }
            #pragma unroll
            for (int o = 1; o < 16; o <<= 1)
                rs += __shfl_xor_sync(0xffffffffu, rs, o);
            lrow[i] = lrow[i] * cf + rs;
            if (tx == 0) corr[(ty << 2) + i] = cf;
            #pragma unroll
            for (int j = 0; j < 4; j++)
                PsT[((tx << 2) + j) * 65 + (ty << 2) + i] = sf[i][j];
        }
        __syncthreads();

        // Rescale accumulators (factor depends on t only)
        float cf2[4];
        #pragma unroll
        for (int j = 0; j < 4; j++) cf2[j] = corr[(tx << 2) + j];
        #pragma unroll
        for (int i = 0; i < 4; i++)
            #pragma unroll
            for (int j = 0; j < 4; j++) acc[i][j] *= cf2[j];

        // GEMM2: A[c][t] += sum_s V[c][s]*P[t][s]; thread owns c=ty*4+i, t=tx*4+j
        #pragma unroll 8
        for (int s = 0; s < 64; s++) {
            float va[4], pa[4];
            #pragma unroll
            for (int i = 0; i < 4; i++) va[i] = VsT[s * 65 + (ty << 2) + i];
            #pragma unroll
            for (int j = 0; j < 4; j++) pa[j] = PsT[s * 65 + (tx << 2) + j];
            #pragma unroll
            for (int i = 0; i < 4; i++)
                #pragma unroll
                for (int j = 0; j < 4; j++)
                    acc[i][j] = fmaf(va[i], pa[j], acc[i][j]);
        }
    }

    // Broadcast row sums to GEMM2 thread mapping, normalize, write out
    if (tx == 0) {
        #pragma unroll
        for (int i = 0; i < 4; i++) lbuf[(ty << 2) + i] = lrow[i];
    }
    __syncthreads();
    float linv[4];
    #pragma unroll
    for (int j = 0; j < 4; j++) linv[j] = 1.0f / lbuf[(tx << 2) + j];

    float* ob = out + ((size_t)b * 512 + h * 64) * 1024;
    #pragma unroll
    for (int i = 0; i < 4; i++) {
        float4 r;
        r.x = acc[i][0] * linv[0];
        r.y = acc[i][1] * linv[1];
        r.z = acc[i][2] * linv[2];
        r.w = acc[i][3] * linv[3];
        *(float4*)(ob + (size_t)((ty << 2) + i) * 1024 + t0 + (tx << 2)) = r;
    }
}

// ---------------------------------------------------------------------------
extern "C" void kernel_launch(void* const* d_in, const int* in_sizes, int n_in,
                              void* d_out, int out_size) {
    const float* x      = (const float*)d_in[0];
    const float* gs     = (const float*)d_in[1];
    const float* gb     = (const float*)d_in[2];
    const float* qkv_w  = (const float*)d_in[3];
    const float* qkv_b  = (const float*)d_in[4];
    const float* proj_w = (const float*)d_in[5];
    const float* proj_b = (const float*)d_in[6];
    float* out = (float*)d_out;

    float *xn_p, *qkv_p, *att_p;
    cudaGetSymbolAddress((void**)&xn_p,  g_xn);
    cudaGetSymbolAddress((void**)&qkv_p, g_qkv);
    cudaGetSymbolAddress((void**)&att_p, g_att);

    // 1) GroupNorm
    gn_kernel<<<256, 256>>>(x, gs, gb);

    // 2) QKV projection: [1536,512] @ [512,1024] per batch
    sgemm_kernel<false><<<dim3(8, 12, 8), 256>>>(
        qkv_w, xn_p, qkv_b, nullptr, qkv_p, 1536, 1024, 512);

    // 3) Attention: 64 bh, 16 t-tiles each
    const int attn_smem = (4096 + 4096 + 4160 + 4160 + 128) * 4;  // 66560 B
    cudaFuncSetAttribute(attn_kernel,
                         cudaFuncAttributeMaxDynamicSharedMemorySize, attn_smem);
    attn_kernel<<<dim3(16, 64), 256, attn_smem>>>(qkv_p, att_p);

    // 4) Output projection + bias + residual -> d_out
    sgemm_kernel<true><<<dim3(8, 4, 8), 256>>>(
        proj_w, att_p, proj_b, x, out, 512, 1024, 512);
}

// round 5
// speedup vs baseline: 2.6049x; 2.6049x over previous
#include <cuda_runtime.h>
#include <math.h>

#define BATCH 8
#define CCH   512
#define LL    1024

__device__ float g_xn [BATCH * CCH * LL];        // groupnorm output
__device__ float g_qkv[BATCH * 3 * CCH * LL];    // qkv projections
__device__ float g_att[BATCH * CCH * LL];        // attention output

// ---------------------------------------------------------------------------
// helpers: tf32 convert, m16n8k8 tf32 mma, fast exp (fma-pipe, no MUFU)
// ---------------------------------------------------------------------------
__device__ __forceinline__ unsigned f2tf(float f) {
    unsigned u;
    asm("cvt.rna.tf32.f32 %0, %1;" : "=r"(u) : "f"(f));
    return u;
}

__device__ __forceinline__ void mma8(float* d, const unsigned* a, const unsigned* b) {
    asm("mma.sync.aligned.m16n8k8.row.col.f32.tf32.tf32.f32 "
        "{%0,%1,%2,%3}, {%4,%5,%6,%7}, {%8,%9}, {%0,%1,%2,%3};"
        : "+f"(d[0]), "+f"(d[1]), "+f"(d[2]), "+f"(d[3])
        : "r"(a[0]), "r"(a[1]), "r"(a[2]), "r"(a[3]), "r"(b[0]), "r"(b[1]));
}

__device__ __forceinline__ float fexp(float x) {
    x = fmaxf(x, -87.0f);
    const float L2E = 1.4426950408889634f;
    float t  = fmaf(x, L2E, 12582912.0f);          // round-to-nearest-int trick
    float ti = t - 12582912.0f;
    float f  = fmaf(x, L2E, -ti);                  // frac in [-0.5, 0.5]
    int   i  = __float_as_int(t) - 0x4B400000;     // integer part
    float p  = 0.0013333558f;
    p = fmaf(p, f, 0.0096181291f);
    p = fmaf(p, f, 0.0555041087f);
    p = fmaf(p, f, 0.2402265070f);
    p = fmaf(p, f, 0.6931471806f);
    p = fmaf(p, f, 1.0f);
    return p * __int_as_float((i + 127) << 23);
}

// ---------------------------------------------------------------------------
// GroupNorm (unchanged; ~15us, HBM-bound)
// ---------------------------------------------------------------------------
__global__ void __launch_bounds__(256) gn_kernel(const float* __restrict__ x,
                                                 const float* __restrict__ gs,
                                                 const float* __restrict__ gb) {
    int bg = blockIdx.x;
    int g  = bg & 31;
    const float4* xp = (const float4*)(x + (size_t)bg * 16 * LL);
    float4*       op = (float4*)(g_xn + (size_t)bg * 16 * LL);
    int tid = threadIdx.x;

    float s = 0.f, ss = 0.f;
    for (int i = tid; i < 4096; i += 256) {
        float4 v = xp[i];
        s  += v.x + v.y + v.z + v.w;
        ss += v.x*v.x + v.y*v.y + v.z*v.z + v.w*v.w;
    }
    #pragma unroll
    for (int o = 16; o > 0; o >>= 1) {
        s  += __shfl_xor_sync(0xffffffffu, s,  o);
        ss += __shfl_xor_sync(0xffffffffu, ss, o);
    }
    __shared__ float red[16];
    int w = tid >> 5;
    if ((tid & 31) == 0) { red[w] = s; red[8 + w] = ss; }
    __syncthreads();
    if (tid == 0) {
        float S = 0.f, SS = 0.f;
        #pragma unroll
        for (int i = 0; i < 8; i++) { S += red[i]; SS += red[8 + i]; }
        float mu  = S * (1.f / 16384.f);
        float var = SS * (1.f / 16384.f) - mu * mu;
        red[0] = mu;
        red[1] = rsqrtf(var + 1e-5f);
    }
    __syncthreads();
    float mu = red[0], rsd = red[1];
    for (int i = tid; i < 4096; i += 256) {
        float4 v = xp[i];
        int c = (g << 4) + (i >> 8);
        float wc = gs[c] * rsd;
        float bc = gb[c] - mu * wc;
        v.x = v.x * wc + bc;  v.y = v.y * wc + bc;
        v.z = v.z * wc + bc;  v.w = v.w * wc + bc;
        op[i] = v;
    }
}

// ---------------------------------------------------------------------------
// tf32 tensor-core GEMM: C[b] = A[M,K] @ B[b][K,N] + bias (+ residual)
// 128x128x16 block tile, 8 warps (each 32x64), m16n8k8 tf32.
// ---------------------------------------------------------------------------
template <bool RESID>
__global__ void __launch_bounds__(256) mma_gemm(
    const float* __restrict__ A,    // [M,K]
    const float* __restrict__ Bg,   // [batch][K,N]
    const float* __restrict__ bias, // [M]
    const float* __restrict__ Rg,   // [batch][M,N]
    float* __restrict__ Cg,         // [batch][M,N]
    int M, int N, int K)
{
    __shared__ unsigned As[128 * 20];   // [m][k], stride 20 (conflict-free frags)
    __shared__ unsigned Bs[16 * 136];   // [k][n], stride 136

    const float* Bp = Bg + (size_t)blockIdx.z * K * N;
    float*       Cp = Cg + (size_t)blockIdx.z * M * N;

    int tid = threadIdx.x, lane = tid & 31, warp = tid >> 5;
    int grp = lane >> 2, tig = lane & 3;
    int wm = (warp & 3) << 5, wn = (warp >> 2) << 6;
    int m0 = blockIdx.y << 7, n0 = blockIdx.x << 7;

    float acc[2][8][4];
    #pragma unroll
    for (int mt = 0; mt < 2; mt++)
        #pragma unroll
        for (int nt = 0; nt < 8; nt++)
            #pragma unroll
            for (int r = 0; r < 4; r++) acc[mt][nt][r] = 0.f;

    for (int k0 = 0; k0 < K; k0 += 16) {
        __syncthreads();
        #pragma unroll
        for (int u = 0; u < 2; u++) {            // A tile 128x16
            int i = (tid << 1) + u;
            int m = i >> 2, q = (i & 3) << 2;
            float4 v = *(const float4*)(A + (size_t)(m0 + m) * K + k0 + q);
            unsigned* d = &As[m * 20 + q];
            d[0] = f2tf(v.x); d[1] = f2tf(v.y); d[2] = f2tf(v.z); d[3] = f2tf(v.w);
        }
        #pragma unroll
        for (int u = 0; u < 2; u++) {            // B tile 16x128
            int i = (tid << 1) + u;
            int kk = i >> 5, q = (i & 31) << 2;
            float4 v = *(const float4*)(Bp + (size_t)(k0 + kk) * N + n0 + q);
            unsigned* d = &Bs[kk * 136 + q];
            d[0] = f2tf(v.x); d[1] = f2tf(v.y); d[2] = f2tf(v.z); d[3] = f2tf(v.w);
        }
        __syncthreads();
        #pragma unroll
        for (int ks = 0; ks < 2; ks++) {
            int kb = ks << 3;
            unsigned af[2][4];
            #pragma unroll
            for (int mt = 0; mt < 2; mt++) {
                int mr = wm + (mt << 4);
                af[mt][0] = As[(mr + grp    ) * 20 + kb + tig];
                af[mt][1] = As[(mr + grp + 8) * 20 + kb + tig];
                af[mt][2] = As[(mr + grp    ) * 20 + kb + tig + 4];
                af[mt][3] = As[(mr + grp + 8) * 20 + kb + tig + 4];
            }
            #pragma unroll
            for (int nt = 0; nt < 8; nt++) {
                unsigned bf[2];
                bf[0] = Bs[(kb + tig    ) * 136 + wn + (nt << 3) + grp];
                bf[1] = Bs[(kb + tig + 4) * 136 + wn + (nt << 3) + grp];
                mma8(acc[0][nt], af[0], bf);
                mma8(acc[1][nt], af[1], bf);
            }
        }
    }

    #pragma unroll
    for (int mt = 0; mt < 2; mt++) {
        int mr0 = m0 + wm + (mt << 4) + grp;
        float b0 = bias[mr0], b1 = bias[mr0 + 8];
        #pragma unroll
        for (int nt = 0; nt < 8; nt++) {
            int n = n0 + wn + (nt << 3) + (tig << 1);
            float2 r0 = make_float2(acc[mt][nt][0] + b0, acc[mt][nt][1] + b0);
            float2 r1 = make_float2(acc[mt][nt][2] + b1, acc[mt][nt][3] + b1);
            if (RESID) {
                const float* Rp = Rg + (size_t)blockIdx.z * M * N;
                float2 v0 = *(const float2*)(Rp + (size_t)mr0 * N + n);
                float2 v1 = *(const float2*)(Rp + (size_t)(mr0 + 8) * N + n);
                r0.x += v0.x; r0.y += v0.y; r1.x += v1.x; r1.y += v1.y;
            }
            *(float2*)(Cp + (size_t)mr0 * N + n) = r0;
            *(float2*)(Cp + (size_t)(mr0 + 8) * N + n) = r1;
        }
    }
}

// ---------------------------------------------------------------------------
// Flash attention, tf32 mma + polynomial exp.
// Block = (t-tile 64, bh), 4 warps (warp w owns t rows [16w,16w+16)).
// All smem tiles in NATURAL [c][x] layout, stride 72 -> conflict-free frag LDS.
// scale 1/8 folded into Q.
// ---------------------------------------------------------------------------
__global__ void __launch_bounds__(128) attn_kernel(const float* __restrict__ qkv,
                                                   float* __restrict__ out) {
    extern __shared__ unsigned sm[];
    unsigned* Qs = sm;               // [c:64][t:64] stride 72
    unsigned* Ks = sm + 64 * 72;     // [c][s]
    unsigned* Vs = sm + 2 * 64 * 72; // [c][s]
    unsigned* Ps = sm + 3 * 64 * 72; // [t][s]

    int bh = blockIdx.y;
    int b = bh >> 3, h = bh & 7;
    int t0 = blockIdx.x << 6;
    const float* qb = qkv + ((size_t)b * 1536 + h * 192) * 1024;
    const float* kb = qb + (size_t)64  * 1024;
    const float* vb = qb + (size_t)128 * 1024;

    int tid = threadIdx.x, lane = tid & 31, warp = tid >> 5;
    int grp = lane >> 2, tig = lane & 3;
    int wt0 = warp << 4;

    // Load Q tile, natural [c][t], scaled, tf32
    for (int i = tid; i < 1024; i += 128) {
        int c = i >> 4, j = (i & 15) << 2;
        float4 v = *(const float4*)(qb + (size_t)c * 1024 + t0 + j);
        unsigned* d = &Qs[c * 72 + j];
        d[0] = f2tf(v.x * 0.125f); d[1] = f2tf(v.y * 0.125f);
        d[2] = f2tf(v.z * 0.125f); d[3] = f2tf(v.w * 0.125f);
    }
    __syncthreads();

    // Q A-fragments hoisted to registers (reused all 16 s-tiles)
    unsigned qa[8][4];
    #pragma unroll
    for (int k = 0; k < 8; k++) {
        int c = (k << 3) + tig;
        qa[k][0] = Qs[c * 72 + wt0 + grp];
        qa[k][1] = Qs[c * 72 + wt0 + grp + 8];
        qa[k][2] = Qs[(c + 4) * 72 + wt0 + grp];
        qa[k][3] = Qs[(c + 4) * 72 + wt0 + grp + 8];
    }

    float oa[8][4];
    #pragma unroll
    for (int nt = 0; nt < 8; nt++)
        #pragma unroll
        for (int r = 0; r < 4; r++) oa[nt][r] = 0.f;
    float m0r = -1e30f, m1r = -1e30f, l0r = 0.f, l1r = 0.f;

    for (int s0 = 0; s0 < 1024; s0 += 64) {
        __syncthreads();   // protect Ks/Vs from prev-iter readers
        for (int i = tid; i < 1024; i += 128) {
            int c = i >> 4, j = (i & 15) << 2;
            float4 kv = *(const float4*)(kb + (size_t)c * 1024 + s0 + j);
            unsigned* dk = &Ks[c * 72 + j];
            dk[0] = f2tf(kv.x); dk[1] = f2tf(kv.y); dk[2] = f2tf(kv.z); dk[3] = f2tf(kv.w);
            float4 vv = *(const float4*)(vb + (size_t)c * 1024 + s0 + j);
            unsigned* dv = &Vs[c * 72 + j];
            dv[0] = f2tf(vv.x); dv[1] = f2tf(vv.y); dv[2] = f2tf(vv.z); dv[3] = f2tf(vv.w);
        }
        __syncthreads();

        // GEMM1: S[t][s] = Q(t,c) * K(c,s)
        float sf[8][4];
        #pragma unroll
        for (int nt = 0; nt < 8; nt++)
            #pragma unroll
            for (int r = 0; r < 4; r++) sf[nt][r] = 0.f;
        #pragma unroll
        for (int k = 0; k < 8; k++) {
            int c = (k << 3) + tig;
            #pragma unroll
            for (int nt = 0; nt < 8; nt++) {
                unsigned bf[2];
                bf[0] = Ks[c * 72 + (nt << 3) + grp];
                bf[1] = Ks[(c + 4) * 72 + (nt << 3) + grp];
                mma8(sf[nt], qa[k], bf);
            }
        }

        // Online softmax (rows grp, grp+8 of this warp; quad-replicated)
        float mx0 = -1e30f, mx1 = -1e30f;
        #pragma unroll
        for (int nt = 0; nt < 8; nt++) {
            mx0 = fmaxf(mx0, fmaxf(sf[nt][0], sf[nt][1]));
            mx1 = fmaxf(mx1, fmaxf(sf[nt][2], sf[nt][3]));
        }
        mx0 = fmaxf(mx0, __shfl_xor_sync(0xffffffffu, mx0, 1));
        mx0 = fmaxf(mx0, __shfl_xor_sync(0xffffffffu, mx0, 2));
        mx1 = fmaxf(mx1, __shfl_xor_sync(0xffffffffu, mx1, 1));
        mx1 = fmaxf(mx1, __shfl_xor_sync(0xffffffffu, mx1, 2));
        float mn0 = fmaxf(m0r, mx0), mn1 = fmaxf(m1r, mx1);
        float cf0 = fexp(m0r - mn0), cf1 = fexp(m1r - mn1);
        m0r = mn0; m1r = mn1;

        float rs0 = 0.f, rs1 = 0.f;
        int pr0 = (wt0 + grp) * 72 + (tig << 1);
        int pr1 = (wt0 + grp + 8) * 72 + (tig << 1);
        #pragma unroll
        for (int nt = 0; nt < 8; nt++) {
            float p0 = fexp(sf[nt][0] - mn0);
            float p1 = fexp(sf[nt][1] - mn0);
            float p2 = fexp(sf[nt][2] - mn1);
            float p3 = fexp(sf[nt][3] - mn1);
            rs0 += p0 + p1; rs1 += p2 + p3;
            Ps[pr0 + (nt << 3)    ] = f2tf(p0);
            Ps[pr0 + (nt << 3) + 1] = f2tf(p1);
            Ps[pr1 + (nt << 3)    ] = f2tf(p2);
            Ps[pr1 + (nt << 3) + 1] = f2tf(p3);
        }
        rs0 += __shfl_xor_sync(0xffffffffu, rs0, 1);
        rs0 += __shfl_xor_sync(0xffffffffu, rs0, 2);
        rs1 += __shfl_xor_sync(0xffffffffu, rs1, 1);
        rs1 += __shfl_xor_sync(0xffffffffu, rs1, 2);
        l0r = l0r * cf0 + rs0;
        l1r = l1r * cf1 + rs1;
        #pragma unroll
        for (int nt = 0; nt < 8; nt++) {
            oa[nt][0] *= cf0; oa[nt][1] *= cf0;
            oa[nt][2] *= cf1; oa[nt][3] *= cf1;
        }
        __syncthreads();

        // GEMM2: O[t][c] += P(t,s) * V(c,s)
        #pragma unroll
        for (int k = 0; k < 8; k++) {
            int s = (k << 3) + tig;
            unsigned pa[4];
            pa[0] = Ps[(wt0 + grp    ) * 72 + s];
            pa[1] = Ps[(wt0 + grp + 8) * 72 + s];
            pa[2] = Ps[(wt0 + grp    ) * 72 + s + 4];
            pa[3] = Ps[(wt0 + grp + 8) * 72 + s + 4];
            #pragma unroll
            for (int nt = 0; nt < 8; nt++) {
                unsigned bf[2];
                bf[0] = Vs[((nt << 3) + grp) * 72 + s];
                bf[1] = Vs[((nt << 3) + grp) * 72 + s + 4];
                mma8(oa[nt], pa, bf);
            }
        }
    }

    float li0 = 1.0f / l0r, li1 = 1.0f / l1r;
    float* ob = out + ((size_t)b * 512 + h * 64) * 1024;
    int tg = t0 + wt0 + grp;
    #pragma unroll
    for (int nt = 0; nt < 8; nt++) {
        int c = (nt << 3) + (tig << 1);
        ob[(size_t)c * 1024 + tg]           = oa[nt][0] * li0;
        ob[(size_t)(c + 1) * 1024 + tg]     = oa[nt][1] * li0;
        ob[(size_t)c * 1024 + tg + 8]       = oa[nt][2] * li1;
        ob[(size_t)(c + 1) * 1024 + tg + 8] = oa[nt][3] * li1;
    }
}

// ---------------------------------------------------------------------------
extern "C" void kernel_launch(void* const* d_in, const int* in_sizes, int n_in,
                              void* d_out, int out_size) {
    const float* x      = (const float*)d_in[0];
    const float* gs     = (const float*)d_in[1];
    const float* gb     = (const float*)d_in[2];
    const float* qkv_w  = (const float*)d_in[3];
    const float* qkv_b  = (const float*)d_in[4];
    const float* proj_w = (const float*)d_in[5];
    const float* proj_b = (const float*)d_in[6];
    float* out = (float*)d_out;

    float *xn_p, *qkv_p, *att_p;
    cudaGetSymbolAddress((void**)&xn_p,  g_xn);
    cudaGetSymbolAddress((void**)&qkv_p, g_qkv);
    cudaGetSymbolAddress((void**)&att_p, g_att);

    // 1) GroupNorm
    gn_kernel<<<256, 256>>>(x, gs, gb);

    // 2) QKV projection: [1536,512] @ [512,1024] x 8
    mma_gemm<false><<<dim3(8, 12, 8), 256>>>(
        qkv_w, xn_p, qkv_b, nullptr, qkv_p, 1536, 1024, 512);

    // 3) Attention
    const int attn_smem = 4 * 64 * 72 * 4;   // 73728 B
    cudaFuncSetAttribute(attn_kernel,
                         cudaFuncAttributeMaxDynamicSharedMemorySize, attn_smem);
    attn_kernel<<<dim3(16, 64), 128, attn_smem>>>(qkv_p, att_p);

    // 4) Output projection + bias + residual
    mma_gemm<true><<<dim3(8, 4, 8), 256>>>(
        proj_w, att_p, proj_b, x, out, 512, 1024, 512);
}

// round 7
// speedup vs baseline: 5.0980x; 1.9571x over previous
#include <cuda_runtime.h>
#include <cuda_bf16.h>
#include <math.h>

#define BATCH 8
#define CCH   512
#define LL    1024

// Scratch (device globals; bf16 intermediates)
__device__ __nv_bfloat16 g_xn [BATCH * CCH * LL];        // groupnorm output
__device__ __nv_bfloat16 g_qkv[BATCH * 3 * CCH * LL];    // qkv projections
__device__ __nv_bfloat16 g_att[BATCH * CCH * LL];        // attention output
__device__ __nv_bfloat16 g_wq [3 * CCH * CCH];           // qkv_w bf16
__device__ __nv_bfloat16 g_wp [CCH * CCH];               // proj_w bf16

// ---------------------------------------------------------------------------
// PTX helpers
// ---------------------------------------------------------------------------
__device__ __forceinline__ void mma16(float* d, const unsigned* a, const unsigned* b) {
    asm("mma.sync.aligned.m16n8k16.row.col.f32.bf16.bf16.f32 "
        "{%0,%1,%2,%3},{%4,%5,%6,%7},{%8,%9},{%0,%1,%2,%3};"
        : "+f"(d[0]), "+f"(d[1]), "+f"(d[2]), "+f"(d[3])
        : "r"(a[0]), "r"(a[1]), "r"(a[2]), "r"(a[3]), "r"(b[0]), "r"(b[1]));
}
__device__ __forceinline__ void ldsm4(unsigned* r, const void* p) {
    unsigned a = (unsigned)__cvta_generic_to_shared(p);
    asm volatile("ldmatrix.sync.aligned.m8n8.x4.shared.b16 {%0,%1,%2,%3}, [%4];"
                 : "=r"(r[0]), "=r"(r[1]), "=r"(r[2]), "=r"(r[3]) : "r"(a));
}
__device__ __forceinline__ void ldsm4t(unsigned* r, const void* p) {
    unsigned a = (unsigned)__cvta_generic_to_shared(p);
    asm volatile("ldmatrix.sync.aligned.m8n8.x4.trans.shared.b16 {%0,%1,%2,%3}, [%4];"
                 : "=r"(r[0]), "=r"(r[1]), "=r"(r[2]), "=r"(r[3]) : "r"(a));
}
__device__ __forceinline__ void cp16(void* s, const void* g) {
    unsigned a = (unsigned)__cvta_generic_to_shared(s);
    asm volatile("cp.async.cg.shared.global [%0], [%1], 16;" :: "r"(a), "l"(g));
}
// exp(0.125*x) on the fma pipe (scale 1/8 folded into the log2e constant)
__device__ __forceinline__ float fexps(float x) {
    x = fmaxf(x, -690.0f);
    const float C = 1.4426950408889634f * 0.125f;
    float t  = fmaf(x, C, 12582912.0f);
    float ti = t - 12582912.0f;
    float f  = fmaf(x, C, -ti);
    int   i  = __float_as_int(t) - 0x4B400000;
    float p  = 0.0013333558f;
    p = fmaf(p, f, 0.0096181291f);
    p = fmaf(p, f, 0.0555041087f);
    p = fmaf(p, f, 0.2402265070f);
    p = fmaf(p, f, 0.6931471806f);
    p = fmaf(p, f, 1.0f);
    return p * __int_as_float((i + 127) << 23);
}

// ---------------------------------------------------------------------------
// Weight convert fp32 -> bf16 (qkv_w then proj_w), 4 elems/thread
// ---------------------------------------------------------------------------
__global__ void __launch_bounds__(256) cvtw_kernel(const float* __restrict__ qw,
                                                   const float* __restrict__ pw) {
    int i = blockIdx.x * 256 + threadIdx.x;
    const float* src; __nv_bfloat16* dst; int j;
    if (i < 196608) { src = qw; dst = g_wq; j = i; }
    else            { src = pw; dst = g_wp; j = i - 196608; }
    float4 v = ((const float4*)src)[j];
    ((__nv_bfloat162*)dst)[2*j]     = __floats2bfloat162_rn(v.x, v.y);
    ((__nv_bfloat162*)dst)[2*j + 1] = __floats2bfloat162_rn(v.z, v.w);
}

// ---------------------------------------------------------------------------
// GroupNorm -> bf16 output
// ---------------------------------------------------------------------------
__global__ void __launch_bounds__(256) gn_kernel(const float* __restrict__ x,
                                                 const float* __restrict__ gs,
                                                 const float* __restrict__ gb) {
    int bg = blockIdx.x;
    int g  = bg & 31;
    const float4* xp = (const float4*)(x + (size_t)bg * 16 * LL);
    __nv_bfloat162* op = (__nv_bfloat162*)(g_xn + (size_t)bg * 16 * LL);
    int tid = threadIdx.x;

    float s = 0.f, ss = 0.f;
    for (int i = tid; i < 4096; i += 256) {
        float4 v = xp[i];
        s  += v.x + v.y + v.z + v.w;
        ss += v.x*v.x + v.y*v.y + v.z*v.z + v.w*v.w;
    }
    #pragma unroll
    for (int o = 16; o > 0; o >>= 1) {
        s  += __shfl_xor_sync(0xffffffffu, s,  o);
        ss += __shfl_xor_sync(0xffffffffu, ss, o);
    }
    __shared__ float red[16];
    int w = tid >> 5;
    if ((tid & 31) == 0) { red[w] = s; red[8 + w] = ss; }
    __syncthreads();
    if (tid == 0) {
        float S = 0.f, SS = 0.f;
        #pragma unroll
        for (int i = 0; i < 8; i++) { S += red[i]; SS += red[8 + i]; }
        float mu  = S * (1.f / 16384.f);
        float var = SS * (1.f / 16384.f) - mu * mu;
        red[0] = mu;
        red[1] = rsqrtf(var + 1e-5f);
    }
    __syncthreads();
    float mu = red[0], rsd = red[1];
    for (int i = tid; i < 4096; i += 256) {
        float4 v = xp[i];
        int c = (g << 4) + (i >> 8);
        float wc = gs[c] * rsd;
        float bc = gb[c] - mu * wc;
        op[2*i]     = __floats2bfloat162_rn(v.x * wc + bc, v.y * wc + bc);
        op[2*i + 1] = __floats2bfloat162_rn(v.z * wc + bc, v.w * wc + bc);
    }
}

// ---------------------------------------------------------------------------
// bf16 tensor-core GEMM: C[b] = A[M,K] @ B[b][K,N] + bias (+ residual)
// 128x128x32 block tile, 8 warps (32x64 each), m16n8k16, ldmatrix,
// cp.async double-buffered.
// ---------------------------------------------------------------------------
template <bool RESID, typename OutT>
__global__ void __launch_bounds__(256) mma_gemm(
    const __nv_bfloat16* __restrict__ A,    // [M,K]
    const __nv_bfloat16* __restrict__ Bg,   // [batch][K,N]
    const float* __restrict__ bias,         // [M]
    const float* __restrict__ Rg,           // [batch][M,N] fp32 (RESID)
    OutT* __restrict__ Cg,                  // [batch][M,N]
    int M, int N, int K)
{
    __shared__ __nv_bfloat16 As[2][128 * 40];   // [m][k] stride 40 halves (80B)
    __shared__ __nv_bfloat16 Bs[2][32 * 136];   // [k][n] stride 136 halves (272B)

    const __nv_bfloat16* Bp = Bg + (size_t)blockIdx.z * K * N;
    OutT*                Cp = Cg + (size_t)blockIdx.z * M * N;

    int tid = threadIdx.x, lane = tid & 31, warp = tid >> 5;
    int grp = lane >> 2, tig = lane & 3;
    int wm = (warp & 3) << 5, wn = (warp >> 2) << 6;
    int m0 = blockIdx.y << 7, n0 = blockIdx.x << 7;

    float acc[2][8][4];
    #pragma unroll
    for (int mt = 0; mt < 2; mt++)
        #pragma unroll
        for (int nt = 0; nt < 8; nt++)
            #pragma unroll
            for (int r = 0; r < 4; r++) acc[mt][nt][r] = 0.f;

    const __nv_bfloat16* Ap = A + (size_t)m0 * K;
    const __nv_bfloat16* Bq = Bp + n0;

    // A tile: 128 rows x 32 halves = 512 x 16B chunks; B tile: 32 x 128 = 512
    auto load = [&](int buf, int k0) {
        #pragma unroll
        for (int u = 0; u < 2; u++) {
            int t = tid + (u << 8);
            int m = t >> 2, c = (t & 3) << 3;
            cp16(&As[buf][m * 40 + c], Ap + (size_t)m * K + k0 + c);
            int k = t >> 4, n = (t & 15) << 3;
            cp16(&Bs[buf][k * 136 + n], Bq + (size_t)(k0 + k) * N + n);
        }
        asm volatile("cp.async.commit_group;");
    };

    int nkt = K >> 5;
    load(0, 0);
    for (int kt = 0; kt < nkt; kt++) {
        int buf = kt & 1;
        if (kt + 1 < nkt) {
            load(buf ^ 1, (kt + 1) << 5);
            asm volatile("cp.async.wait_group 1;");
        } else {
            asm volatile("cp.async.wait_group 0;");
        }
        __syncthreads();

        #pragma unroll
        for (int ks = 0; ks < 2; ks++) {
            int kb = ks << 4;
            unsigned af[2][4];
            #pragma unroll
            for (int mt = 0; mt < 2; mt++)
                ldsm4(af[mt], &As[buf][(wm + (mt << 4) + (lane & 15)) * 40
                                       + kb + ((lane >> 4) << 3)]);
            #pragma unroll
            for (int ntp = 0; ntp < 4; ntp++) {
                unsigned bf4[4];
                ldsm4t(bf4, &Bs[buf][(kb + (lane & 15)) * 136
                                     + wn + (ntp << 4) + ((lane >> 4) << 3)]);
                mma16(acc[0][2*ntp],     af[0], bf4);
                mma16(acc[0][2*ntp + 1], af[0], bf4 + 2);
                mma16(acc[1][2*ntp],     af[1], bf4);
                mma16(acc[1][2*ntp + 1], af[1], bf4 + 2);
            }
        }
        __syncthreads();
    }

    #pragma unroll
    for (int mt = 0; mt < 2; mt++) {
        int mr0 = m0 + wm + (mt << 4) + grp;
        float b0 = bias[mr0], b1 = bias[mr0 + 8];
        #pragma unroll
        for (int nt = 0; nt < 8; nt++) {
            int n = n0 + wn + (nt << 3) + (tig << 1);
            float2 r0 = make_float2(acc[mt][nt][0] + b0, acc[mt][nt][1] + b0);
            float2 r1 = make_float2(acc[mt][nt][2] + b1, acc[mt][nt][3] + b1);
            if (RESID) {
                const float* Rp = Rg + (size_t)blockIdx.z * M * N;
                float2 v0 = *(const float2*)(Rp + (size_t)mr0 * N + n);
                float2 v1 = *(const float2*)(Rp + (size_t)(mr0 + 8) * N + n);
                r0.x += v0.x; r0.y += v0.y; r1.x += v1.x; r1.y += v1.y;
            }
            if (sizeof(OutT) == 4) {
                *(float2*)((float*)Cp + (size_t)mr0 * N + n) = r0;
                *(float2*)((float*)Cp + (size_t)(mr0 + 8) * N + n) = r1;
            } else {
                *(__nv_bfloat162*)((__nv_bfloat16*)Cp + (size_t)mr0 * N + n) =
                    __floats2bfloat162_rn(r0.x, r0.y);
                *(__nv_bfloat162*)((__nv_bfloat16*)Cp + (size_t)(mr0 + 8) * N + n) =
                    __floats2bfloat162_rn(r1.x, r1.y);
            }
        }
    }
}

// ---------------------------------------------------------------------------
// Flash attention, bf16 mma + ldmatrix + polynomial exp.
// Block = (t-tile 64, bh), 4 warps (warp w -> t rows [16w,16w+16)).
// smem tiles natural [c][x] layout, stride 72 halves (144 B) -> per-phase
// conflict-free ldmatrix. Logit scale 1/8 folded into fexps.
// ---------------------------------------------------------------------------
__global__ void __launch_bounds__(128) attn_kernel(const __nv_bfloat16* __restrict__ qkv,
                                                   __nv_bfloat16* __restrict__ out) {
    __shared__ __nv_bfloat16 Qs[64 * 72];   // [c][t]
    __shared__ __nv_bfloat16 Ks[64 * 72];   // [c][s]
    __shared__ __nv_bfloat16 Vs[64 * 72];   // [c][s]
    __shared__ __nv_bfloat16 Ps[64 * 72];   // [t][s]

    int bh = blockIdx.y;
    int b = bh >> 3, h = bh & 7;
    int t0 = blockIdx.x << 6;
    const __nv_bfloat16* qb = qkv + ((size_t)b * 1536 + h * 192) * 1024;
    const __nv_bfloat16* kp = qb + (size_t)64  * 1024;
    const __nv_bfloat16* vp = qb + (size_t)128 * 1024;

    int tid = threadIdx.x, lane = tid & 31, warp = tid >> 5;
    int grp = lane >> 2, tig = lane & 3;
    int wt0 = warp << 4;

    // Q tile load (natural layout, 16B chunks)
    for (int i = tid; i < 512; i += 128) {
        int c = i >> 3, j = (i & 7) << 3;
        *(uint4*)&Qs[c * 72 + j] = *(const uint4*)(qb + (size_t)c * 1024 + t0 + j);
    }
    __syncthreads();

    // Hoist Q A-fragments (trans ldmatrix from [c][t]) for all 4 k-steps
    unsigned qa[4][4];
    #pragma unroll
    for (int kb = 0; kb < 4; kb++)
        ldsm4t(qa[kb], &Qs[((kb << 4) + ((lane >> 4) << 3) + (lane & 7)) * 72
                           + wt0 + (((lane >> 3) & 1) << 3)]);

    float oa[8][4];
    #pragma unroll
    for (int nt = 0; nt < 8; nt++)
        #pragma unroll
        for (int r = 0; r < 4; r++) oa[nt][r] = 0.f;
    float m0r = -1e30f, m1r = -1e30f, l0r = 0.f, l1r = 0.f;

    for (int s0 = 0; s0 < 1024; s0 += 64) {
        __syncthreads();
        for (int i = tid; i < 512; i += 128) {
            int c = i >> 3, j = (i & 7) << 3;
            *(uint4*)&Ks[c * 72 + j] = *(const uint4*)(kp + (size_t)c * 1024 + s0 + j);
            *(uint4*)&Vs[c * 72 + j] = *(const uint4*)(vp + (size_t)c * 1024 + s0 + j);
        }
        __syncthreads();

        // GEMM1: S[t][s] = Q(t,c) * K(c,s)
        float sf[8][4];
        #pragma unroll
        for (int nt = 0; nt < 8; nt++)
            #pragma unroll
            for (int r = 0; r < 4; r++) sf[nt][r] = 0.f;
        #pragma unroll
        for (int kb = 0; kb < 4; kb++) {
            #pragma unroll
            for (int ntp = 0; ntp < 4; ntp++) {
                unsigned bf4[4];
                ldsm4t(bf4, &Ks[((kb << 4) + (lane & 15)) * 72
                                + (ntp << 4) + ((lane >> 4) << 3)]);
                mma16(sf[2*ntp],     qa[kb], bf4);
                mma16(sf[2*ntp + 1], qa[kb], bf4 + 2);
            }
        }

        // Online softmax (logits scaled by 1/8 inside fexps; max is monotone)
        float mx0 = -1e30f, mx1 = -1e30f;
        #pragma unroll
        for (int nt = 0; nt < 8; nt++) {
            mx0 = fmaxf(mx0, fmaxf(sf[nt][0], sf[nt][1]));
            mx1 = fmaxf(mx1, fmaxf(sf[nt][2], sf[nt][3]));
        }
        mx0 = fmaxf(mx0, __shfl_xor_sync(0xffffffffu, mx0, 1));
        mx0 = fmaxf(mx0, __shfl_xor_sync(0xffffffffu, mx0, 2));
        mx1 = fmaxf(mx1, __shfl_xor_sync(0xffffffffu, mx1, 1));
        mx1 = fmaxf(mx1, __shfl_xor_sync(0xffffffffu, mx1, 2));
        float mn0 = fmaxf(m0r, mx0), mn1 = fmaxf(m1r, mx1);
        float cf0 = fexps(m0r - mn0), cf1 = fexps(m1r - mn1);
        m0r = mn0; m1r = mn1;

        float rs0 = 0.f, rs1 = 0.f;
        int pr0 = (wt0 + grp) * 72 + (tig << 1);
        int pr1 = (wt0 + grp + 8) * 72 + (tig << 1);
        #pragma unroll
        for (int nt = 0; nt < 8; nt++) {
            float p0 = fexps(sf[nt][0] - mn0);
            float p1 = fexps(sf[nt][1] - mn0);
            float p2 = fexps(sf[nt][2] - mn1);
            float p3 = fexps(sf[nt][3] - mn1);
            rs0 += p0 + p1; rs1 += p2 + p3;
            *(__nv_bfloat162*)&Ps[pr0 + (nt << 3)] = __floats2bfloat162_rn(p0, p1);
            *(__nv_bfloat162*)&Ps[pr1 + (nt << 3)] = __floats2bfloat162_rn(p2, p3);
        }
        rs0 += __shfl_xor_sync(0xffffffffu, rs0, 1);
        rs0 += __shfl_xor_sync(0xffffffffu, rs0, 2);
        rs1 += __shfl_xor_sync(0xffffffffu, rs1, 1);
        rs1 += __shfl_xor_sync(0xffffffffu, rs1, 2);
        l0r = l0r * cf0 + rs0;
        l1r = l1r * cf1 + rs1;
        #pragma unroll
        for (int nt = 0; nt < 8; nt++) {
            oa[nt][0] *= cf0; oa[nt][1] *= cf0;
            oa[nt][2] *= cf1; oa[nt][3] *= cf1;
        }
        __syncthreads();

        // GEMM2: O[t][c] += P(t,s) * V(c,s)
        #pragma unroll
        for (int kb = 0; kb < 4; kb++) {
            unsigned pa[4];
            ldsm4(pa, &Ps[(wt0 + (lane & 15)) * 72 + (kb << 4) + ((lane >> 4) << 3)]);
            #pragma unroll
            for (int ntp = 0; ntp < 4; ntp++) {
                unsigned bf4[4];
                ldsm4(bf4, &Vs[((ntp << 4) + ((lane >> 4) << 3) + (lane & 7)) * 72
                               + (kb << 4) + (((lane >> 3) & 1) << 3)]);
                mma16(oa[2*ntp],     pa, bf4);
                mma16(oa[2*ntp + 1], pa, bf4 + 2);
            }
        }
    }

    float li0 = 1.0f / l0r, li1 = 1.0f / l1r;
    __nv_bfloat16* ob = out + ((size_t)b * 512 + h * 64) * 1024;
    int tg = t0 + wt0 + grp;
    #pragma unroll
    for (int nt = 0; nt < 8; nt++) {
        int c = (nt << 3) + (tig << 1);
        ob[(size_t)c * 1024 + tg]           = __float2bfloat16(oa[nt][0] * li0);
        ob[(size_t)(c + 1) * 1024 + tg]     = __float2bfloat16(oa[nt][1] * li0);
        ob[(size_t)c * 1024 + tg + 8]       = __float2bfloat16(oa[nt][2] * li1);
        ob[(size_t)(c + 1) * 1024 + tg + 8] = __float2bfloat16(oa[nt][3] * li1);
    }
}

// ---------------------------------------------------------------------------
extern "C" void kernel_launch(void* const* d_in, const int* in_sizes, int n_in,
                              void* d_out, int out_size) {
    const float* x      = (const float*)d_in[0];
    const float* gs     = (const float*)d_in[1];
    const float* gb     = (const float*)d_in[2];
    const float* qkv_w  = (const float*)d_in[3];
    const float* qkv_b  = (const float*)d_in[4];
    const float* proj_w = (const float*)d_in[5];
    const float* proj_b = (const float*)d_in[6];
    float* out = (float*)d_out;

    __nv_bfloat16 *xn_p, *qkv_p, *att_p, *wq_p, *wp_p;
    cudaGetSymbolAddress((void**)&xn_p,  g_xn);
    cudaGetSymbolAddress((void**)&qkv_p, g_qkv);
    cudaGetSymbolAddress((void**)&att_p, g_att);
    cudaGetSymbolAddress((void**)&wq_p,  g_wq);
    cudaGetSymbolAddress((void**)&wp_p,  g_wp);

    // 0) weights fp32 -> bf16
    cvtw_kernel<<<1024, 256>>>(qkv_w, proj_w);
    // 1) GroupNorm -> bf16
    gn_kernel<<<256, 256>>>(x, gs, gb);
    // 2) QKV projection: [1536,512] @ [512,1024] x 8 -> bf16
    mma_gemm<false, __nv_bfloat16><<<dim3(8, 12, 8), 256>>>(
        wq_p, xn_p, qkv_b, nullptr, qkv_p, 1536, 1024, 512);
    // 3) Attention -> bf16
    attn_kernel<<<dim3(16, 64), 128>>>(qkv_p, att_p);
    // 4) Output projection + bias + fp32 residual -> d_out
    mma_gemm<true, float><<<dim3(8, 4, 8), 256>>>(
        wp_p, att_p, proj_b, x, out, 512, 1024, 512);
}

// round 8
// speedup vs baseline: 6.2068x; 1.2175x over previous
#include <cuda_runtime.h>
#include <cuda_bf16.h>
#include <math.h>

#define BATCH 8
#define CCH   512
#define LL    1024

// Scratch (device globals; bf16 intermediates)
__device__ __nv_bfloat16 g_xn [BATCH * CCH * LL];        // groupnorm output
__device__ __nv_bfloat16 g_qkv[BATCH * 3 * CCH * LL];    // qkv projections
__device__ __nv_bfloat16 g_att[BATCH * CCH * LL];        // attention output
__device__ __nv_bfloat16 g_wq [3 * CCH * CCH];           // qkv_w bf16
__device__ __nv_bfloat16 g_wp [CCH * CCH];               // proj_w bf16

// ---------------------------------------------------------------------------
// PTX helpers
// ---------------------------------------------------------------------------
__device__ __forceinline__ void mma16(float* d, const unsigned* a, const unsigned* b) {
    asm("mma.sync.aligned.m16n8k16.row.col.f32.bf16.bf16.f32 "
        "{%0,%1,%2,%3},{%4,%5,%6,%7},{%8,%9},{%0,%1,%2,%3};"
        : "+f"(d[0]), "+f"(d[1]), "+f"(d[2]), "+f"(d[3])
        : "r"(a[0]), "r"(a[1]), "r"(a[2]), "r"(a[3]), "r"(b[0]), "r"(b[1]));
}
__device__ __forceinline__ void ldsm4(unsigned* r, const void* p) {
    unsigned a = (unsigned)__cvta_generic_to_shared(p);
    asm volatile("ldmatrix.sync.aligned.m8n8.x4.shared.b16 {%0,%1,%2,%3}, [%4];"
                 : "=r"(r[0]), "=r"(r[1]), "=r"(r[2]), "=r"(r[3]) : "r"(a));
}
__device__ __forceinline__ void ldsm4t(unsigned* r, const void* p) {
    unsigned a = (unsigned)__cvta_generic_to_shared(p);
    asm volatile("ldmatrix.sync.aligned.m8n8.x4.trans.shared.b16 {%0,%1,%2,%3}, [%4];"
                 : "=r"(r[0]), "=r"(r[1]), "=r"(r[2]), "=r"(r[3]) : "r"(a));
}
__device__ __forceinline__ void cp16(void* s, const void* g) {
    unsigned a = (unsigned)__cvta_generic_to_shared(s);
    asm volatile("cp.async.cg.shared.global [%0], [%1], 16;" :: "r"(a), "l"(g));
}

// Packed f32x2 helpers (Blackwell dual-fp32 pipe)
__device__ __forceinline__ unsigned long long pkf2(float x, float y) {
    unsigned long long r;
    asm("mov.b64 %0, {%1, %2};" : "=l"(r) : "f"(x), "f"(y));
    return r;
}
__device__ __forceinline__ unsigned long long fma2(unsigned long long a,
                                                   unsigned long long b,
                                                   unsigned long long c) {
    unsigned long long d;
    asm("fma.rn.f32x2 %0, %1, %2, %3;" : "=l"(d) : "l"(a), "l"(b), "l"(c));
    return d;
}
// Pairwise exp(0.125*x) — poly on the packed-f32 pipe, scale via ALU bit math.
__device__ __forceinline__ void fexps2(float x0, float x1, float& r0, float& r1) {
    x0 = fmaxf(x0, -690.0f);
    x1 = fmaxf(x1, -690.0f);
    const float C  = 1.4426950408889634f * 0.125f;   // log2e/8
    const float MG = 12582912.0f;                    // 1.5*2^23
    unsigned long long X  = pkf2(x0, x1);
    unsigned long long Cv = pkf2(C, C);
    unsigned long long Mv = pkf2(MG, MG);
    unsigned long long T  = fma2(X, Cv, Mv);                 // round(x*C) + MG
    unsigned long long NT = fma2(T, pkf2(-1.f, -1.f), Mv);   // -(round int part)
    unsigned long long F  = fma2(X, Cv, NT);                 // frac in [-0.5,0.5]
    unsigned long long P  = fma2(pkf2(0.0013333558f, 0.0013333558f), F,
                                 pkf2(0.0096181291f, 0.0096181291f));
    P = fma2(P, F, pkf2(0.0555041087f, 0.0555041087f));
    P = fma2(P, F, pkf2(0.2402265070f, 0.2402265070f));
    P = fma2(P, F, pkf2(0.6931471806f, 0.6931471806f));
    P = fma2(P, F, pkf2(1.0f, 1.0f));
    unsigned t0, t1;
    asm("mov.b64 {%0, %1}, %2;" : "=r"(t0), "=r"(t1) : "l"(T));
    unsigned s0 = (t0 + (127u - 0x4B400000u)) << 23;         // 2^i bits
    unsigned s1 = (t1 + (127u - 0x4B400000u)) << 23;
    unsigned long long SC;
    asm("mov.b64 %0, {%1, %2};" : "=l"(SC) : "r"(s0), "r"(s1));
    unsigned long long R;
    asm("mul.rn.f32x2 %0, %1, %2;" : "=l"(R) : "l"(P), "l"(SC));
    asm("mov.b64 {%0, %1}, %2;" : "=f"(r0), "=f"(r1) : "l"(R));
}

// ---------------------------------------------------------------------------
// Weight convert fp32 -> bf16 (qkv_w then proj_w)
// ---------------------------------------------------------------------------
__global__ void __launch_bounds__(256) cvtw_kernel(const float* __restrict__ qw,
                                                   const float* __restrict__ pw) {
    int i = blockIdx.x * 256 + threadIdx.x;
    const float* src; __nv_bfloat16* dst; int j;
    if (i < 196608) { src = qw; dst = g_wq; j = i; }
    else            { src = pw; dst = g_wp; j = i - 196608; }
    float4 v = ((const float4*)src)[j];
    ((__nv_bfloat162*)dst)[2*j]     = __floats2bfloat162_rn(v.x, v.y);
    ((__nv_bfloat162*)dst)[2*j + 1] = __floats2bfloat162_rn(v.z, v.w);
}

// ---------------------------------------------------------------------------
// GroupNorm -> bf16 output
// ---------------------------------------------------------------------------
__global__ void __launch_bounds__(256) gn_kernel(const float* __restrict__ x,
                                                 const float* __restrict__ gs,
                                                 const float* __restrict__ gb) {
    int bg = blockIdx.x;
    int g  = bg & 31;
    const float4* xp = (const float4*)(x + (size_t)bg * 16 * LL);
    __nv_bfloat162* op = (__nv_bfloat162*)(g_xn + (size_t)bg * 16 * LL);
    int tid = threadIdx.x;

    float s = 0.f, ss = 0.f;
    for (int i = tid; i < 4096; i += 256) {
        float4 v = xp[i];
        s  += v.x + v.y + v.z + v.w;
        ss += v.x*v.x + v.y*v.y + v.z*v.z + v.w*v.w;
    }
    #pragma unroll
    for (int o = 16; o > 0; o >>= 1) {
        s  += __shfl_xor_sync(0xffffffffu, s,  o);
        ss += __shfl_xor_sync(0xffffffffu, ss, o);
    }
    __shared__ float red[16];
    int w = tid >> 5;
    if ((tid & 31) == 0) { red[w] = s; red[8 + w] = ss; }
    __syncthreads();
    if (tid == 0) {
        float S = 0.f, SS = 0.f;
        #pragma unroll
        for (int i = 0; i < 8; i++) { S += red[i]; SS += red[8 + i]; }
        float mu  = S * (1.f / 16384.f);
        float var = SS * (1.f / 16384.f) - mu * mu;
        red[0] = mu;
        red[1] = rsqrtf(var + 1e-5f);
    }
    __syncthreads();
    float mu = red[0], rsd = red[1];
    for (int i = tid; i < 4096; i += 256) {
        float4 v = xp[i];
        int c = (g << 4) + (i >> 8);
        float wc = gs[c] * rsd;
        float bc = gb[c] - mu * wc;
        op[2*i]     = __floats2bfloat162_rn(v.x * wc + bc, v.y * wc + bc);
        op[2*i + 1] = __floats2bfloat162_rn(v.z * wc + bc, v.w * wc + bc);
    }
}

// ---------------------------------------------------------------------------
// bf16 tensor-core GEMM (unchanged): C[b] = A[M,K] @ B[b][K,N] + bias (+resid)
// ---------------------------------------------------------------------------
template <bool RESID, typename OutT>
__global__ void __launch_bounds__(256) mma_gemm(
    const __nv_bfloat16* __restrict__ A,
    const __nv_bfloat16* __restrict__ Bg,
    const float* __restrict__ bias,
    const float* __restrict__ Rg,
    OutT* __restrict__ Cg,
    int M, int N, int K)
{
    __shared__ __nv_bfloat16 As[2][128 * 40];
    __shared__ __nv_bfloat16 Bs[2][32 * 136];

    const __nv_bfloat16* Bp = Bg + (size_t)blockIdx.z * K * N;
    OutT*                Cp = Cg + (size_t)blockIdx.z * M * N;

    int tid = threadIdx.x, lane = tid & 31, warp = tid >> 5;
    int grp = lane >> 2, tig = lane & 3;
    int wm = (warp & 3) << 5, wn = (warp >> 2) << 6;
    int m0 = blockIdx.y << 7, n0 = blockIdx.x << 7;

    float acc[2][8][4];
    #pragma unroll
    for (int mt = 0; mt < 2; mt++)
        #pragma unroll
        for (int nt = 0; nt < 8; nt++)
            #pragma unroll
            for (int r = 0; r < 4; r++) acc[mt][nt][r] = 0.f;

    const __nv_bfloat16* Ap = A + (size_t)m0 * K;
    const __nv_bfloat16* Bq = Bp + n0;

    auto load = [&](int buf, int k0) {
        #pragma unroll
        for (int u = 0; u < 2; u++) {
            int t = tid + (u << 8);
            int m = t >> 2, c = (t & 3) << 3;
            cp16(&As[buf][m * 40 + c], Ap + (size_t)m * K + k0 + c);
            int k = t >> 4, n = (t & 15) << 3;
            cp16(&Bs[buf][k * 136 + n], Bq + (size_t)(k0 + k) * N + n);
        }
        asm volatile("cp.async.commit_group;");
    };

    int nkt = K >> 5;
    load(0, 0);
    for (int kt = 0; kt < nkt; kt++) {
        int buf = kt & 1;
        if (kt + 1 < nkt) {
            load(buf ^ 1, (kt + 1) << 5);
            asm volatile("cp.async.wait_group 1;");
        } else {
            asm volatile("cp.async.wait_group 0;");
        }
        __syncthreads();

        #pragma unroll
        for (int ks = 0; ks < 2; ks++) {
            int kb = ks << 4;
            unsigned af[2][4];
            #pragma unroll
            for (int mt = 0; mt < 2; mt++)
                ldsm4(af[mt], &As[buf][(wm + (mt << 4) + (lane & 15)) * 40
                                       + kb + ((lane >> 4) << 3)]);
            #pragma unroll
            for (int ntp = 0; ntp < 4; ntp++) {
                unsigned bf4[4];
                ldsm4t(bf4, &Bs[buf][(kb + (lane & 15)) * 136
                                     + wn + (ntp << 4) + ((lane >> 4) << 3)]);
                mma16(acc[0][2*ntp],     af[0], bf4);
                mma16(acc[0][2*ntp + 1], af[0], bf4 + 2);
                mma16(acc[1][2*ntp],     af[1], bf4);
                mma16(acc[1][2*ntp + 1], af[1], bf4 + 2);
            }
        }
        __syncthreads();
    }

    #pragma unroll
    for (int mt = 0; mt < 2; mt++) {
        int mr0 = m0 + wm + (mt << 4) + grp;
        float b0 = bias[mr0], b1 = bias[mr0 + 8];
        #pragma unroll
        for (int nt = 0; nt < 8; nt++) {
            int n = n0 + wn + (nt << 3) + (tig << 1);
            float2 r0 = make_float2(acc[mt][nt][0] + b0, acc[mt][nt][1] + b0);
            float2 r1 = make_float2(acc[mt][nt][2] + b1, acc[mt][nt][3] + b1);
            if (RESID) {
                const float* Rp = Rg + (size_t)blockIdx.z * M * N;
                float2 v0 = *(const float2*)(Rp + (size_t)mr0 * N + n);
                float2 v1 = *(const float2*)(Rp + (size_t)(mr0 + 8) * N + n);
                r0.x += v0.x; r0.y += v0.y; r1.x += v1.x; r1.y += v1.y;
            }
            if (sizeof(OutT) == 4) {
                *(float2*)((float*)Cp + (size_t)mr0 * N + n) = r0;
                *(float2*)((float*)Cp + (size_t)(mr0 + 8) * N + n) = r1;
            } else {
                *(__nv_bfloat162*)((__nv_bfloat16*)Cp + (size_t)mr0 * N + n) =
                    __floats2bfloat162_rn(r0.x, r0.y);
                *(__nv_bfloat162*)((__nv_bfloat16*)Cp + (size_t)(mr0 + 8) * N + n) =
                    __floats2bfloat162_rn(r1.x, r1.y);
            }
        }
    }
}

// ---------------------------------------------------------------------------
// Flash attention: bf16 mma + ldmatrix, cp.async double-buffered K/V,
// one __syncthreads per s-tile, pairwise f32x2 exp.
// ---------------------------------------------------------------------------
__global__ void __launch_bounds__(128) attn_kernel(const __nv_bfloat16* __restrict__ qkv,
                                                   __nv_bfloat16* __restrict__ out) {
    extern __shared__ __nv_bfloat16 sm[];
    __nv_bfloat16* Qs  = sm;                 // [c:64][t:64] stride 72
    __nv_bfloat16* Ks0 = sm + 4608;          // double-buffered [c][s]
    __nv_bfloat16* Vs0 = sm + 3 * 4608;      // double-buffered [c][s]
    __nv_bfloat16* Ps  = sm + 5 * 4608;      // [t][s]

    int bh = blockIdx.y;
    int b = bh >> 3, h = bh & 7;
    int t0 = blockIdx.x << 6;
    const __nv_bfloat16* qb = qkv + ((size_t)b * 1536 + h * 192) * 1024;
    const __nv_bfloat16* kp = qb + (size_t)64  * 1024;
    const __nv_bfloat16* vp = qb + (size_t)128 * 1024;

    int tid = threadIdx.x, lane = tid & 31, warp = tid >> 5;
    int grp = lane >> 2, tig = lane & 3;
    int wt0 = warp << 4;

    auto loadKV = [&](int buf, int s0) {
        __nv_bfloat16* Kb = Ks0 + buf * 4608;
        __nv_bfloat16* Vb = Vs0 + buf * 4608;
        #pragma unroll
        for (int u = 0; u < 4; u++) {
            int i = tid + (u << 7);
            int c = i >> 3, j = (i & 7) << 3;
            cp16(Kb + c * 72 + j, kp + (size_t)c * 1024 + s0 + j);
            cp16(Vb + c * 72 + j, vp + (size_t)c * 1024 + s0 + j);
        }
        asm volatile("cp.async.commit_group;");
    };

    // Prefetch KV tile 0, then load Q while it flies
    loadKV(0, 0);
    for (int i = tid; i < 512; i += 128) {
        int c = i >> 3, j = (i & 7) << 3;
        *(uint4*)&Qs[c * 72 + j] = *(const uint4*)(qb + (size_t)c * 1024 + t0 + j);
    }
    __syncthreads();

    // Hoist Q A-fragments for all 4 k-steps
    unsigned qa[4][4];
    #pragma unroll
    for (int kb = 0; kb < 4; kb++)
        ldsm4t(qa[kb], &Qs[((kb << 4) + ((lane >> 4) << 3) + (lane & 7)) * 72
                           + wt0 + (((lane >> 3) & 1) << 3)]);

    float oa[8][4];
    #pragma unroll
    for (int nt = 0; nt < 8; nt++)
        #pragma unroll
        for (int r = 0; r < 4; r++) oa[nt][r] = 0.f;
    float m0r = -1e30f, m1r = -1e30f, l0r = 0.f, l1r = 0.f;

    for (int it = 0; it < 16; it++) {
        int buf = it & 1;
        __nv_bfloat16* Kb = Ks0 + buf * 4608;
        __nv_bfloat16* Vb = Vs0 + buf * 4608;

        asm volatile("cp.async.wait_group 0;");
        __syncthreads();                         // tile it visible; buf^1 free
        if (it < 15) loadKV(buf ^ 1, (it + 1) << 6);   // overlaps all compute below

        // GEMM1: S[t][s] = Q(t,c) * K(c,s)
        float sf[8][4];
        #pragma unroll
        for (int nt = 0; nt < 8; nt++)
            #pragma unroll
            for (int r = 0; r < 4; r++) sf[nt][r] = 0.f;
        #pragma unroll
        for (int kb = 0; kb < 4; kb++) {
            #pragma unroll
            for (int ntp = 0; ntp < 4; ntp++) {
                unsigned bf4[4];
                ldsm4t(bf4, &Kb[((kb << 4) + (lane & 15)) * 72
                                + (ntp << 4) + ((lane >> 4) << 3)]);
                mma16(sf[2*ntp],     qa[kb], bf4);
                mma16(sf[2*ntp + 1], qa[kb], bf4 + 2);
            }
        }

        // Online softmax (scale 1/8 folded into fexps2; max is monotone)
        float mx0 = -1e30f, mx1 = -1e30f;
        #pragma unroll
        for (int nt = 0; nt < 8; nt++) {
            mx0 = fmaxf(mx0, fmaxf(sf[nt][0], sf[nt][1]));
            mx1 = fmaxf(mx1, fmaxf(sf[nt][2], sf[nt][3]));
        }
        mx0 = fmaxf(mx0, __shfl_xor_sync(0xffffffffu, mx0, 1));
        mx0 = fmaxf(mx0, __shfl_xor_sync(0xffffffffu, mx0, 2));
        mx1 = fmaxf(mx1, __shfl_xor_sync(0xffffffffu, mx1, 1));
        mx1 = fmaxf(mx1, __shfl_xor_sync(0xffffffffu, mx1, 2));
        float mn0 = fmaxf(m0r, mx0), mn1 = fmaxf(m1r, mx1);
        float cf0, cf1;
        fexps2(m0r - mn0, m1r - mn1, cf0, cf1);
        m0r = mn0; m1r = mn1;

        float rs0 = 0.f, rs1 = 0.f;
        int pr0 = (wt0 + grp) * 72 + (tig << 1);
        int pr1 = (wt0 + grp + 8) * 72 + (tig << 1);
        #pragma unroll
        for (int nt = 0; nt < 8; nt++) {
            float p0, p1, p2, p3;
            fexps2(sf[nt][0] - mn0, sf[nt][1] - mn0, p0, p1);
            fexps2(sf[nt][2] - mn1, sf[nt][3] - mn1, p2, p3);
            rs0 += p0 + p1; rs1 += p2 + p3;
            *(__nv_bfloat162*)&Ps[pr0 + (nt << 3)] = __floats2bfloat162_rn(p0, p1);
            *(__nv_bfloat162*)&Ps[pr1 + (nt << 3)] = __floats2bfloat162_rn(p2, p3);
        }
        rs0 += __shfl_xor_sync(0xffffffffu, rs0, 1);
        rs0 += __shfl_xor_sync(0xffffffffu, rs0, 2);
        rs1 += __shfl_xor_sync(0xffffffffu, rs1, 1);
        rs1 += __shfl_xor_sync(0xffffffffu, rs1, 2);
        l0r = l0r * cf0 + rs0;
        l1r = l1r * cf1 + rs1;
        #pragma unroll
        for (int nt = 0; nt < 8; nt++) {
            oa[nt][0] *= cf0; oa[nt][1] *= cf0;
            oa[nt][2] *= cf1; oa[nt][3] *= cf1;
        }
        __syncwarp();   // warp-private Ps rows: warp-level ordering suffices

        // GEMM2: O[t][c] += P(t,s) * V(c,s)
        #pragma unroll
        for (int kb = 0; kb < 4; kb++) {
            unsigned pa[4];
            ldsm4(pa, &Ps[(wt0 + (lane & 15)) * 72 + (kb << 4) + ((lane >> 4) << 3)]);
            #pragma unroll
            for (int ntp = 0; ntp < 4; ntp++) {
                unsigned bf4[4];
                ldsm4(bf4, &Vb[((ntp << 4) + ((lane >> 4) << 3) + (lane & 7)) * 72
                               + (kb << 4) + (((lane >> 3) & 1) << 3)]);
                mma16(oa[2*ntp],     pa, bf4);
                mma16(oa[2*ntp + 1], pa, bf4 + 2);
            }
        }
    }

    float li0 = 1.0f / l0r, li1 = 1.0f / l1r;
    __nv_bfloat16* ob = out + ((size_t)b * 512 + h * 64) * 1024;
    int tg = t0 + wt0 + grp;
    #pragma unroll
    for (int nt = 0; nt < 8; nt++) {
        int c = (nt << 3) + (tig << 1);
        ob[(size_t)c * 1024 + tg]           = __float2bfloat16(oa[nt][0] * li0);
        ob[(size_t)(c + 1) * 1024 + tg]     = __float2bfloat16(oa[nt][1] * li0);
        ob[(size_t)c * 1024 + tg + 8]       = __float2bfloat16(oa[nt][2] * li1);
        ob[(size_t)(c + 1) * 1024 + tg + 8] = __float2bfloat16(oa[nt][3] * li1);
    }
}

// ---------------------------------------------------------------------------
extern "C" void kernel_launch(void* const* d_in, const int* in_sizes, int n_in,
                              void* d_out, int out_size) {
    const float* x      = (const float*)d_in[0];
    const float* gs     = (const float*)d_in[1];
    const float* gb     = (const float*)d_in[2];
    const float* qkv_w  = (const float*)d_in[3];
    const float* qkv_b  = (const float*)d_in[4];
    const float* proj_w = (const float*)d_in[5];
    const float* proj_b = (const float*)d_in[6];
    float* out = (float*)d_out;

    __nv_bfloat16 *xn_p, *qkv_p, *att_p, *wq_p, *wp_p;
    cudaGetSymbolAddress((void**)&xn_p,  g_xn);
    cudaGetSymbolAddress((void**)&qkv_p, g_qkv);
    cudaGetSymbolAddress((void**)&att_p, g_att);
    cudaGetSymbolAddress((void**)&wq_p,  g_wq);
    cudaGetSymbolAddress((void**)&wp_p,  g_wp);

    // 0) weights fp32 -> bf16
    cvtw_kernel<<<1024, 256>>>(qkv_w, proj_w);
    // 1) GroupNorm -> bf16
    gn_kernel<<<256, 256>>>(x, gs, gb);
    // 2) QKV projection: [1536,512] @ [512,1024] x 8 -> bf16
    mma_gemm<false, __nv_bfloat16><<<dim3(8, 12, 8), 256>>>(
        wq_p, xn_p, qkv_b, nullptr, qkv_p, 1536, 1024, 512);
    // 3) Attention -> bf16 (6 x 4608 halves = 55296 B dynamic smem)
    const int attn_smem = 6 * 4608 * 2;
    cudaFuncSetAttribute(attn_kernel,
                         cudaFuncAttributeMaxDynamicSharedMemorySize, attn_smem);
    attn_kernel<<<dim3(16, 64), 128, attn_smem>>>(qkv_p, att_p);
    // 4) Output projection + bias + fp32 residual -> d_out
    mma_gemm<true, float><<<dim3(8, 4, 8), 256>>>(
        wp_p, att_p, proj_b, x, out, 512, 1024, 512);
}